// round 3
// baseline (speedup 1.0000x reference)
#include <cuda_runtime.h>
#include <cuda_bf16.h>
#include <cstdint>

// ---------------- constants ----------------
#define AS   36      // A-chunk smem row stride (32 + 4 pad)
#define BS   132     // B-chunk smem row stride (128 + 4 pad)
#define ACT  132     // activation smem row stride
#define R0F  16896   // region0 floats: act (128*132); A double-buf (2*128*36=9216) aliases it
#define BOFF 16896
#define BBUF 4224    // one B buffer: 32*132
#define MISC 25344   // 16896 + 2*4224
#define SMEM_F 25856 // +512 misc floats
#define SMEM_BYTES (SMEM_F * 4)

// ---------------- device scratch (no allocs allowed) ----------------
__device__ float g_W0r[384 * 128];  // tf32-rounded W0 rows 0..383, [k][n]
__device__ float g_W1p[128 * 128];  // tf32-rounded diag(a0)*W1
__device__ float g_W2p[128 * 128];  // tf32-rounded diag(a1)*W2
__device__ float g_U[64 * 128];     // U'[b][n] = b0[n] + sum_k u[b,k]*W0[384+k,n]
__device__ float g_b1p[128];
__device__ float g_b2p[128];
__device__ float g_a2v[128];
__device__ float g_c2v[128];

// ---------------- helpers ----------------
__device__ __forceinline__ uint32_t f2tf(float x) {
    uint32_t r;
    asm("cvt.rna.tf32.f32 %0, %1;" : "=r"(r) : "f"(x));
    return r;
}

__device__ __forceinline__ void cp16(float* s, const float* g) {
    uint32_t sa = (uint32_t)__cvta_generic_to_shared(s);
    asm volatile("cp.async.cg.shared.global [%0], [%1], 16;" :: "r"(sa), "l"(g) : "memory");
}
#define CPC asm volatile("cp.async.commit_group;" ::: "memory")
#define CPW(n) asm volatile("cp.async.wait_group %0;" :: "n"(n) : "memory")

__device__ __forceinline__ void mma8(float* c, uint32_t a0, uint32_t a1, uint32_t a2, uint32_t a3,
                                     uint32_t b0, uint32_t b1) {
    asm volatile(
        "mma.sync.aligned.m16n8k8.row.col.f32.tf32.tf32.f32 "
        "{%0,%1,%2,%3}, {%4,%5,%6,%7}, {%8,%9}, {%0,%1,%2,%3};"
        : "+f"(c[0]), "+f"(c[1]), "+f"(c[2]), "+f"(c[3])
        : "r"(a0), "r"(a1), "r"(a2), "r"(a3), "r"(b0), "r"(b1));
}

// One 32-k chunk: warp computes 32x64 tile. 16 MMA + 8 A-LDS(+cvt) + 16 B-LDS per k-step.
__device__ __forceinline__ void mma_chunk(const float* aP, int as_, const float* bP,
                                          float* acc, int rbase, int cbase, int g, int t4) {
#pragma unroll
    for (int kk = 0; kk < 4; kk++) {
        const int k0 = kk * 8;
        uint32_t a[8];
#pragma unroll
        for (int rt = 0; rt < 2; rt++) {
            const float* ap = aP + (rbase + rt * 16 + g) * as_ + k0 + t4;
            a[rt * 4 + 0] = f2tf(ap[0]);
            a[rt * 4 + 1] = f2tf(ap[8 * as_]);
            a[rt * 4 + 2] = f2tf(ap[4]);
            a[rt * 4 + 3] = f2tf(ap[8 * as_ + 4]);
        }
#pragma unroll
        for (int ct = 0; ct < 8; ct++) {
            const float* bp = bP + (k0 + t4) * BS + cbase + ct * 8 + g;
            uint32_t b0 = __float_as_uint(bp[0]);        // weights pre-rounded to tf32
            uint32_t b1 = __float_as_uint(bp[4 * BS]);
            mma8(&acc[(ct * 2 + 0) * 4], a[0], a[1], a[2], a[3], b0, b1);
            mma8(&acc[(ct * 2 + 1) * 4], a[4], a[5], a[6], a[7], b0, b1);
        }
    }
}

// ---------------- prep kernels ----------------
__global__ void prep_round0(const float* __restrict__ W0) {
    int i = blockIdx.x * 256 + threadIdx.x;  // 0 .. 384*128-1
    g_W0r[i] = __uint_as_float(f2tf(W0[i]));
}

__global__ void prep_fold(const float* __restrict__ W1, const float* __restrict__ b1,
                          const float* __restrict__ W2, const float* __restrict__ b2,
                          const float* __restrict__ g0, const float* __restrict__ be0,
                          const float* __restrict__ m0, const float* __restrict__ v0,
                          const float* __restrict__ g1, const float* __restrict__ be1,
                          const float* __restrict__ m1, const float* __restrict__ v1,
                          const float* __restrict__ g2, const float* __restrict__ be2,
                          const float* __restrict__ m2, const float* __restrict__ v2) {
    __shared__ float a0s[128], c0s[128], a1s[128], c1s[128];
    int n = threadIdx.x;
    float a0 = g0[n] * rsqrtf(v0[n] + 1e-5f);
    a0s[n] = a0; c0s[n] = be0[n] - m0[n] * a0;
    float a1 = g1[n] * rsqrtf(v1[n] + 1e-5f);
    a1s[n] = a1; c1s[n] = be1[n] - m1[n] * a1;
    float a2 = g2[n] * rsqrtf(v2[n] + 1e-5f);
    g_a2v[n] = a2; g_c2v[n] = be2[n] - m2[n] * a2;
    __syncthreads();
    float s1 = b1[n], s2 = b2[n];
    for (int k = 0; k < 128; k++) {
        float w1 = W1[k * 128 + n], w2 = W2[k * 128 + n];
        g_W1p[k * 128 + n] = __uint_as_float(f2tf(a0s[k] * w1));
        s1 += c0s[k] * w1;
        g_W2p[k * 128 + n] = __uint_as_float(f2tf(a1s[k] * w2));
        s2 += c1s[k] * w2;
    }
    g_b1p[n] = s1;
    g_b2p[n] = s2;
}

__global__ void prep_U(const float* __restrict__ u, const float* __restrict__ W0,
                       const float* __restrict__ b0) {
    __shared__ float ub[128];
    int b = blockIdx.x, n = threadIdx.x;
    ub[n] = u[b * 128 + n];
    __syncthreads();
    float acc = b0[n];
    for (int k = 0; k < 128; k++) acc += ub[k] * W0[(384 + k) * 128 + n];
    g_U[b * 128 + n] = acc;
}

// ---------------- main kernel ----------------
__global__ void __launch_bounds__(256, 2)
megnet_main(const float* __restrict__ src, const float* __restrict__ dst_,
            const float* __restrict__ edg, const int* __restrict__ batch,
            float* __restrict__ out, int E) {
    extern __shared__ float sm[];
    float* sB = sm + BOFF;
    int* sBatch = (int*)(sm + MISC);
    float* sBias = sm + MISC + 128;
    float* sA2 = sm + MISC + 256;
    float* sC2 = sm + MISC + 384;

    const int tid = threadIdx.x;
    const int lane = tid & 31, w = tid >> 5;
    const int g = lane >> 2, t4 = lane & 3;
    const int rbase = (w & 3) * 32, cbase = (w >> 2) * 64;
    const int ebase = blockIdx.x * 128;

    if (tid < 128) {
        int e = ebase + tid;
        if (e >= E) e = E - 1;
        sBatch[tid] = batch[e];
    }

    // ---- prefetch lambdas ----
    auto PFA = [&](int c, int buf) {   // layer-0 A chunk: tensor c>>2, cols (c&3)*32
        const float* T = (c < 4) ? src : ((c < 8) ? dst_ : edg);
        const int coff = (c & 3) * 32;
        float* d = sm + buf * 128 * AS;
#pragma unroll
        for (int i = 0; i < 4; i++) {
            int f = tid + i * 256;
            int row = f >> 3, c4 = f & 7;
            int e = ebase + row;
            if (e >= E) e = E - 1;
            cp16(d + row * AS + c4 * 4, T + (size_t)e * 128 + coff + c4 * 4);
        }
    };
    auto PFB = [&](const float* Wp, int kb, int buf) {  // 32x128 weight chunk
        float* d = sB + buf * BBUF;
#pragma unroll
        for (int i = 0; i < 4; i++) {
            int f = tid + i * 256;
            int kr = f >> 5, c4 = f & 31;
            cp16(d + kr * BS + c4 * 4, Wp + (size_t)(kb + kr) * 128 + c4 * 4);
        }
    };

    float acc[64];
#pragma unroll
    for (int i = 0; i < 64; i++) acc[i] = 0.f;

    // ================= GEMM0: K = 384 (12 chunks of 32) =================
    PFA(0, 0); PFB(g_W0r, 0, 0); CPC;
    PFA(1, 1); PFB(g_W0r, 32, 1); CPC;
    for (int c = 0; c < 12; c++) {
        if (c < 11) { CPW(1); } else { CPW(0); }
        __syncthreads();
        mma_chunk(sm + (c & 1) * 128 * AS, AS, sB + (c & 1) * BBUF, acc, rbase, cbase, g, t4);
        __syncthreads();
        if (c + 2 < 12) { PFA(c + 2, c & 1); PFB(g_W0r, (c + 2) * 32, c & 1); CPC; }
    }

    // prefetch W1 chunks 0,1 (sB free after final barrier above)
    PFB(g_W1p, 0, 0); CPC;
    PFB(g_W1p, 32, 1); CPC;

    // ---- epilogue0: + U'[batch], relu -> act (aliases A buffers; GEMM0 done) ----
#pragma unroll
    for (int ct = 0; ct < 8; ct++) {
        const int col = cbase + ct * 8 + t4 * 2;
#pragma unroll
        for (int rt = 0; rt < 2; rt++) {
            int ra = rbase + rt * 16 + g, rb = ra + 8;
            float2 ua = *(const float2*)&g_U[sBatch[ra] * 128 + col];
            float2 ub = *(const float2*)&g_U[sBatch[rb] * 128 + col];
            float* a4 = &acc[(ct * 2 + rt) * 4];
            float2 va = {fmaxf(a4[0] + ua.x, 0.f), fmaxf(a4[1] + ua.y, 0.f)};
            float2 vb = {fmaxf(a4[2] + ub.x, 0.f), fmaxf(a4[3] + ub.y, 0.f)};
            *(float2*)&sm[ra * ACT + col] = va;
            *(float2*)&sm[rb * ACT + col] = vb;
        }
    }
    if (tid < 128) sBias[tid] = g_b1p[tid];
#pragma unroll
    for (int i = 0; i < 64; i++) acc[i] = 0.f;
    __syncthreads();

    // ================= GEMM1: K = 128 (4 chunks), A = act in smem =================
    for (int c = 0; c < 4; c++) {
        if (c < 3) { CPW(1); } else { CPW(0); }
        __syncthreads();
        mma_chunk(sm + c * 32, ACT, sB + (c & 1) * BBUF, acc, rbase, cbase, g, t4);
        __syncthreads();
        if (c + 2 < 4) { PFB(g_W1p, (c + 2) * 32, c & 1); CPC; }
    }

    PFB(g_W2p, 0, 0); CPC;
    PFB(g_W2p, 32, 1); CPC;

    // ---- epilogue1: + b1', relu -> act (in place) ----
#pragma unroll
    for (int ct = 0; ct < 8; ct++) {
        const int col = cbase + ct * 8 + t4 * 2;
        float bb0 = sBias[col], bb1 = sBias[col + 1];
#pragma unroll
        for (int rt = 0; rt < 2; rt++) {
            int ra = rbase + rt * 16 + g, rb = ra + 8;
            float* a4 = &acc[(ct * 2 + rt) * 4];
            float2 va = {fmaxf(a4[0] + bb0, 0.f), fmaxf(a4[1] + bb1, 0.f)};
            float2 vb = {fmaxf(a4[2] + bb0, 0.f), fmaxf(a4[3] + bb1, 0.f)};
            *(float2*)&sm[ra * ACT + col] = va;
            *(float2*)&sm[rb * ACT + col] = vb;
        }
    }
    __syncthreads();   // all epilogue1 reads of sBias done
    if (tid < 128) {
        sBias[tid] = g_b2p[tid];
        sA2[tid] = g_a2v[tid];
        sC2[tid] = g_c2v[tid];
    }
#pragma unroll
    for (int i = 0; i < 64; i++) acc[i] = 0.f;
    __syncthreads();

    // ================= GEMM2: K = 128 (4 chunks) =================
    for (int c = 0; c < 4; c++) {
        if (c < 3) { CPW(1); } else { CPW(0); }
        __syncthreads();
        mma_chunk(sm + c * 32, ACT, sB + (c & 1) * BBUF, acc, rbase, cbase, g, t4);
        __syncthreads();
        if (c + 2 < 4) { PFB(g_W2p, (c + 2) * 32, c & 1); CPC; }
    }

    // ---- final epilogue: + b2', relu, BN2 affine, store ----
    const int Ev = E - ebase;
#pragma unroll
    for (int ct = 0; ct < 8; ct++) {
        const int col = cbase + ct * 8 + t4 * 2;
        float bb0 = sBias[col], bb1 = sBias[col + 1];
        float aa0 = sA2[col], aa1 = sA2[col + 1];
        float cc0 = sC2[col], cc1 = sC2[col + 1];
#pragma unroll
        for (int rt = 0; rt < 2; rt++) {
            int ra = rbase + rt * 16 + g, rb = ra + 8;
            float* a4 = &acc[(ct * 2 + rt) * 4];
            if (ra < Ev) {
                float2 v = {fmaxf(a4[0] + bb0, 0.f) * aa0 + cc0,
                            fmaxf(a4[1] + bb1, 0.f) * aa1 + cc1};
                *(float2*)&out[(size_t)(ebase + ra) * 128 + col] = v;
            }
            if (rb < Ev) {
                float2 v = {fmaxf(a4[2] + bb0, 0.f) * aa0 + cc0,
                            fmaxf(a4[3] + bb1, 0.f) * aa1 + cc1};
                *(float2*)&out[(size_t)(ebase + rb) * 128 + col] = v;
            }
        }
    }
}

// ---------------- launch ----------------
extern "C" void kernel_launch(void* const* d_in, const int* in_sizes, int n_in,
                              void* d_out, int out_size) {
    const float* src  = (const float*)d_in[0];
    const float* dest = (const float*)d_in[1];
    const float* edge = (const float*)d_in[2];
    const float* u    = (const float*)d_in[3];
    const int*   batch = (const int*)d_in[4];
    const float* W0 = (const float*)d_in[5];
    const float* b0 = (const float*)d_in[6];
    const float* W1 = (const float*)d_in[7];
    const float* b1 = (const float*)d_in[8];
    const float* W2 = (const float*)d_in[9];
    const float* b2 = (const float*)d_in[10];
    const float* g0 = (const float*)d_in[11];
    const float* be0 = (const float*)d_in[12];
    const float* m0 = (const float*)d_in[13];
    const float* v0 = (const float*)d_in[14];
    const float* g1 = (const float*)d_in[15];
    const float* be1 = (const float*)d_in[16];
    const float* m1 = (const float*)d_in[17];
    const float* v1 = (const float*)d_in[18];
    const float* g2 = (const float*)d_in[19];
    const float* be2 = (const float*)d_in[20];
    const float* m2 = (const float*)d_in[21];
    const float* v2 = (const float*)d_in[22];

    int E = in_sizes[0] / 128;

    cudaFuncSetAttribute(megnet_main, cudaFuncAttributeMaxDynamicSharedMemorySize, SMEM_BYTES);

    prep_round0<<<192, 256>>>(W0);
    prep_fold<<<1, 128>>>(W1, b1, W2, b2, g0, be0, m0, v0, g1, be1, m1, v1, g2, be2, m2, v2);
    prep_U<<<64, 128>>>(u, W0, b0);
    megnet_main<<<(E + 127) / 128, 256, SMEM_BYTES>>>(src, dest, edge, batch, (float*)d_out, E);
}

// round 6
// speedup vs baseline: 1.4356x; 1.4356x over previous
#include <cuda_runtime.h>
#include <cuda_fp16.h>
#include <cstdint>

// ---------------- smem layout (bytes) ----------------
#define STG_STRIDE 144                  // fp32 staging row: 128B data + 16B pad
#define STG_BYTES  (128 * 144)          // 18432 per buffer, 2 buffers at 0
#define ACT_BASE   (2 * STG_BYTES)      // 36864: activations 128 x 272B (fp16, padded)
#define ACT_STRIDE 272
#define A16_BYTES  (128 * 80)           // 10240: layer-0 fp16 A chunk (aliases ACT region)
#define BB_BASE    (ACT_BASE + 128 * 272)   // 71680: B fp16 chunks, 3 stages x 10240
#define BB_BYTES   (128 * 80)
#define MISC_BASE  (BB_BASE + 3 * BB_BYTES) // 102400
#define SMEM_BYTES (MISC_BASE + 2560)       // 104960

// ---------------- device scratch ----------------
__device__ __half g_W0h[128 * 384];  // [n][k] fp16 W0^T (k = 0..383)
__device__ __half g_W1h[128 * 128];  // [n][k] fp16( a0[k] * W1[k][n] )
__device__ __half g_W2h[128 * 128];  // [n][k] fp16( a1[k] * W2[k][n] )
__device__ float  g_U[64 * 128];     // U'[b][n] = b0[n] + u[b]@W0[384:,n]
__device__ float  g_b1p[128];
__device__ float  g_b2p[128];
__device__ float  g_a2v[128];
__device__ float  g_c2v[128];

// ---------------- helpers ----------------
__device__ __forceinline__ uint32_t smem_u32(const void* p) {
    uint32_t a;
    asm("{ .reg .u64 t; cvta.to.shared.u64 t, %1; cvt.u32.u64 %0, t; }" : "=r"(a) : "l"(p));
    return a;
}
__device__ __forceinline__ void cp16(void* dst, const void* src) {
    uint32_t sa = smem_u32(dst);
    asm volatile("cp.async.cg.shared.global [%0], [%1], 16;" :: "r"(sa), "l"(src) : "memory");
}
#define CPC asm volatile("cp.async.commit_group;" ::: "memory")
#define CPW(n) asm volatile("cp.async.wait_group %0;" :: "n"(n) : "memory")

__device__ __forceinline__ void ldsm4(uint32_t& r0, uint32_t& r1, uint32_t& r2, uint32_t& r3,
                                      uint32_t addr) {
    asm volatile("ldmatrix.sync.aligned.m8n8.x4.shared.b16 {%0,%1,%2,%3}, [%4];"
                 : "=r"(r0), "=r"(r1), "=r"(r2), "=r"(r3) : "r"(addr));
}
__device__ __forceinline__ void mma16816(float* c, const uint32_t* a, uint32_t b0, uint32_t b1) {
    asm volatile(
        "mma.sync.aligned.m16n8k16.row.col.f32.f16.f16.f32 "
        "{%0,%1,%2,%3}, {%4,%5,%6,%7}, {%8,%9}, {%0,%1,%2,%3};"
        : "+f"(c[0]), "+f"(c[1]), "+f"(c[2]), "+f"(c[3])
        : "r"(a[0]), "r"(a[1]), "r"(a[2]), "r"(a[3]), "r"(b0), "r"(b1));
}
__device__ __forceinline__ uint32_t h2u(__half2 h) {
    union { __half2 h; uint32_t u; } cv;
    cv.h = h;
    return cv.u;
}

// ---------------- prep kernels ----------------
__global__ void prep_W0h(const float* __restrict__ W0) {
    int i = blockIdx.x * 256 + threadIdx.x;  // 0 .. 128*384-1
    int n = i / 384, k = i - n * 384;
    g_W0h[i] = __float2half(W0[k * 128 + n]);
}

__global__ void prep_fold(const float* __restrict__ W1, const float* __restrict__ b1,
                          const float* __restrict__ W2, const float* __restrict__ b2,
                          const float* __restrict__ g0, const float* __restrict__ be0,
                          const float* __restrict__ m0, const float* __restrict__ v0,
                          const float* __restrict__ g1, const float* __restrict__ be1,
                          const float* __restrict__ m1, const float* __restrict__ v1,
                          const float* __restrict__ g2, const float* __restrict__ be2,
                          const float* __restrict__ m2, const float* __restrict__ v2) {
    __shared__ float a0s[128], c0s[128], a1s[128], c1s[128];
    int n = threadIdx.x;
    float a0 = g0[n] * rsqrtf(v0[n] + 1e-5f);
    a0s[n] = a0; c0s[n] = be0[n] - m0[n] * a0;
    float a1 = g1[n] * rsqrtf(v1[n] + 1e-5f);
    a1s[n] = a1; c1s[n] = be1[n] - m1[n] * a1;
    float a2 = g2[n] * rsqrtf(v2[n] + 1e-5f);
    g_a2v[n] = a2; g_c2v[n] = be2[n] - m2[n] * a2;
    __syncthreads();
    float s1 = b1[n], s2 = b2[n];
    for (int k = 0; k < 128; k++) {
        float w1 = W1[k * 128 + n], w2 = W2[k * 128 + n];
        g_W1h[n * 128 + k] = __float2half(a0s[k] * w1);
        s1 += c0s[k] * w1;
        g_W2h[n * 128 + k] = __float2half(a1s[k] * w2);
        s2 += c1s[k] * w2;
    }
    g_b1p[n] = s1;
    g_b2p[n] = s2;
}

__global__ void prep_U(const float* __restrict__ u, const float* __restrict__ W0,
                       const float* __restrict__ b0) {
    __shared__ float ub[128];
    int b = blockIdx.x, n = threadIdx.x;
    ub[n] = u[b * 128 + n];
    __syncthreads();
    float acc = b0[n];
    for (int k = 0; k < 128; k++) acc += ub[k] * W0[(384 + k) * 128 + n];
    g_U[b * 128 + n] = acc;
}

// ---------------- main kernel ----------------
__global__ void __launch_bounds__(256, 2)
megnet_main(const float* __restrict__ src, const float* __restrict__ dst_,
            const float* __restrict__ edg, const int* __restrict__ batch,
            float* __restrict__ out, int E) {
    extern __shared__ char sm[];
    const uint32_t sbase = smem_u32(sm);
    const int tid = threadIdx.x;
    const int w = tid >> 5, lane = tid & 31;
    const int gid = lane >> 2, tig = lane & 3;
    const int rbase = (w & 3) * 32, cbase = (w >> 2) * 64;
    const int ebase = blockIdx.x * 128;

    int* sBatch = (int*)(sm + MISC_BASE);
    float* sB1 = (float*)(sm + MISC_BASE + 512);
    float* sB2 = (float*)(sm + MISC_BASE + 1024);
    float* sA2 = (float*)(sm + MISC_BASE + 1536);
    float* sC2 = (float*)(sm + MISC_BASE + 2048);

    if (tid < 128) {
        int e = ebase + tid;
        if (e >= E) e = E - 1;
        sBatch[tid] = batch[e];
        sB1[tid] = g_b1p[tid];
        sB2[tid] = g_b2p[tid];
        sA2[tid] = g_a2v[tid];
        sC2[tid] = g_c2v[tid];
    }

    // ---- prefetch: layer-0 fp32 A chunk into padded staging ----
    auto PFA = [&](int cg) {
        const float* T = (cg < 4) ? src : ((cg < 8) ? dst_ : edg);
        const int coff = (cg & 3) * 32;
        char* base = sm + (cg & 1) * STG_BYTES;
#pragma unroll
        for (int i = 0; i < 4; i++) {
            int f = tid + i * 256;           // 1024 16B-units
            int row = f >> 3, u = f & 7;
            int e = ebase + row;
            if (e >= E) e = E - 1;
            cp16(base + row * STG_STRIDE + u * 16,
                 (const char*)(T + (size_t)e * 128 + coff) + u * 16);
        }
    };
    // ---- prefetch: fp16 weight chunk [128n x 32k] into padded B buffer ----
    auto PFB = [&](int cg) {
        const __half* Wh; int kb, ldk;
        if (cg < 12)      { Wh = g_W0h; kb = cg * 32;        ldk = 384; }
        else if (cg < 16) { Wh = g_W1h; kb = (cg - 12) * 32; ldk = 128; }
        else              { Wh = g_W2h; kb = (cg - 16) * 32; ldk = 128; }
        char* base = sm + BB_BASE + (cg % 3) * BB_BYTES;
#pragma unroll
        for (int i = 0; i < 2; i++) {
            int f = tid + i * 256;           // 512 16B-units
            int n = f >> 2, kh = f & 3;
            cp16(base + n * 80 + kh * 16,
                 (const char*)(Wh + (size_t)n * ldk + kb) + kh * 16);
        }
    };
    // ---- convert staged fp32 chunk -> fp16 A buffer (stride 80) ----
    auto CONV = [&](int cg) {
        const int buf = cg & 1;
        const int r = tid & 127, h = tid >> 7;
        const char* sp = sm + buf * STG_BYTES + r * STG_STRIDE + h * 64;
        float4 f0 = *(const float4*)(sp);
        float4 f1 = *(const float4*)(sp + 16);
        float4 f2 = *(const float4*)(sp + 32);
        float4 f3 = *(const float4*)(sp + 48);
        uint4 o0, o1;
        o0.x = h2u(__floats2half2_rn(f0.x, f0.y));
        o0.y = h2u(__floats2half2_rn(f0.z, f0.w));
        o0.z = h2u(__floats2half2_rn(f1.x, f1.y));
        o0.w = h2u(__floats2half2_rn(f1.z, f1.w));
        o1.x = h2u(__floats2half2_rn(f2.x, f2.y));
        o1.y = h2u(__floats2half2_rn(f2.z, f2.w));
        o1.z = h2u(__floats2half2_rn(f3.x, f3.y));
        o1.w = h2u(__floats2half2_rn(f3.z, f3.w));
        char* dp = sm + ACT_BASE + buf * A16_BYTES + r * 80 + h * 32;
        *(uint4*)(dp) = o0;
        *(uint4*)(dp + 16) = o1;
    };

    float acc[2][8][4];
#pragma unroll
    for (int mt = 0; mt < 2; mt++)
#pragma unroll
        for (int nt = 0; nt < 8; nt++)
#pragma unroll
            for (int i = 0; i < 4; i++) acc[mt][nt][i] = 0.f;

    // ---- epilogue: acc -> (+U' or +b1'), relu, fp16 -> activation smem ----
    auto EPI = [&](bool first) {
        __syncthreads();                      // all warps done with previous MMA reads
#pragma unroll
        for (int mt = 0; mt < 2; mt++) {
#pragma unroll
            for (int nt = 0; nt < 8; nt++) {
                const int col = cbase + nt * 8 + 2 * tig;
#pragma unroll
                for (int rh = 0; rh < 2; rh++) {
                    const int row = rbase + mt * 16 + gid + rh * 8;
                    float ax, ay;
                    if (first) {
                        const float2 uv = *(const float2*)&g_U[(size_t)sBatch[row] * 128 + col];
                        ax = uv.x; ay = uv.y;
                    } else {
                        ax = sB1[col]; ay = sB1[col + 1];
                    }
                    float* c4 = acc[mt][nt];
                    float x = fmaxf(c4[rh * 2 + 0] + ax, 0.f);
                    float y = fmaxf(c4[rh * 2 + 1] + ay, 0.f);
                    *(__half2*)(sm + ACT_BASE + row * ACT_STRIDE + ((col >> 3) << 4) +
                                (col & 7) * 2) = __floats2half2_rn(x, y);
                    c4[rh * 2 + 0] = 0.f;
                    c4[rh * 2 + 1] = 0.f;
                }
            }
        }
    };

    // ---------------- pipeline: 20 chunks (12 + 4 + 4) ----------------
    __syncthreads();     // sBatch/bias tables visible
    PFA(0); PFB(0); CPC;
    PFA(1); PFB(1); CPC;

#pragma unroll 1
    for (int cg = 0; cg < 20; cg++) {
        if (cg == 12) EPI(true);
        else if (cg == 16) EPI(false);

        if (cg < 19) { CPW(1); } else { CPW(0); }
        __syncthreads();          // publish this chunk's cp.async data to ALL threads
        if (cg < 12) {
            CONV(cg);
            __syncthreads();      // publish fp16 conversions before ldmatrix reads
        }
        if (cg + 2 < 20) {
            if (cg + 2 < 12) PFA(cg + 2);
            PFB(cg + 2);
            CPC;
        }

        // ---- MMA for chunk cg: warp tile 32m x 64n, K=32 (2 k-steps of 16) ----
        uint32_t aB; int aS;
        if (cg < 12) { aB = sbase + ACT_BASE + (cg & 1) * A16_BYTES; aS = 80; }
        else {
            aB = sbase + ACT_BASE + ((cg < 16) ? (cg - 12) : (cg - 16)) * 64;
            aS = ACT_STRIDE;
        }
        const uint32_t bB = sbase + BB_BASE + (cg % 3) * BB_BYTES;

#pragma unroll
        for (int ks = 0; ks < 2; ks++) {
            uint32_t a[2][4];
#pragma unroll
            for (int mt = 0; mt < 2; mt++) {
                uint32_t ad = aB + (uint32_t)(rbase + mt * 16 + (lane & 15)) * aS +
                              ks * 32 + (lane >> 4) * 16;
                ldsm4(a[mt][0], a[mt][1], a[mt][2], a[mt][3], ad);
            }
            uint32_t b[4][4];
#pragma unroll
            for (int nt2 = 0; nt2 < 4; nt2++) {
                uint32_t bd = bB + (uint32_t)(cbase + nt2 * 16 + (lane & 7) +
                                              ((lane >> 4) & 1) * 8) * 80 +
                              ks * 32 + ((lane >> 3) & 1) * 16;
                ldsm4(b[nt2][0], b[nt2][1], b[nt2][2], b[nt2][3], bd);
            }
#pragma unroll
            for (int mt = 0; mt < 2; mt++)
#pragma unroll
                for (int nt2 = 0; nt2 < 4; nt2++) {
                    mma16816(acc[mt][nt2 * 2 + 0], a[mt], b[nt2][0], b[nt2][1]);
                    mma16816(acc[mt][nt2 * 2 + 1], a[mt], b[nt2][2], b[nt2][3]);
                }
        }
    }

    // ---------------- final epilogue: + b2', relu, BN2 affine, store ----------------
    const int Ev = E - ebase;
#pragma unroll
    for (int mt = 0; mt < 2; mt++) {
#pragma unroll
        for (int nt = 0; nt < 8; nt++) {
            const int col = cbase + nt * 8 + 2 * tig;
            const float bx = sB2[col], by = sB2[col + 1];
            const float axm = sA2[col], aym = sA2[col + 1];
            const float cxm = sC2[col], cym = sC2[col + 1];
#pragma unroll
            for (int rh = 0; rh < 2; rh++) {
                const int row = rbase + mt * 16 + gid + rh * 8;
                if (row < Ev) {
                    float* c4 = acc[mt][nt];
                    float2 v;
                    v.x = fmaxf(c4[rh * 2 + 0] + bx, 0.f) * axm + cxm;
                    v.y = fmaxf(c4[rh * 2 + 1] + by, 0.f) * aym + cym;
                    *(float2*)&out[(size_t)(ebase + row) * 128 + col] = v;
                }
            }
        }
    }
}

// ---------------- launch ----------------
extern "C" void kernel_launch(void* const* d_in, const int* in_sizes, int n_in,
                              void* d_out, int out_size) {
    const float* src  = (const float*)d_in[0];
    const float* dest = (const float*)d_in[1];
    const float* edge = (const float*)d_in[2];
    const float* u    = (const float*)d_in[3];
    const int*   batch = (const int*)d_in[4];
    const float* W0 = (const float*)d_in[5];
    const float* b0 = (const float*)d_in[6];
    const float* W1 = (const float*)d_in[7];
    const float* b1 = (const float*)d_in[8];
    const float* W2 = (const float*)d_in[9];
    const float* b2 = (const float*)d_in[10];
    const float* g0 = (const float*)d_in[11];
    const float* be0 = (const float*)d_in[12];
    const float* m0 = (const float*)d_in[13];
    const float* v0 = (const float*)d_in[14];
    const float* g1 = (const float*)d_in[15];
    const float* be1 = (const float*)d_in[16];
    const float* m1 = (const float*)d_in[17];
    const float* v1 = (const float*)d_in[18];
    const float* g2 = (const float*)d_in[19];
    const float* be2 = (const float*)d_in[20];
    const float* m2 = (const float*)d_in[21];
    const float* v2 = (const float*)d_in[22];

    int E = in_sizes[0] / 128;

    cudaFuncSetAttribute(megnet_main, cudaFuncAttributeMaxDynamicSharedMemorySize, SMEM_BYTES);

    prep_W0h<<<192, 256>>>(W0);
    prep_fold<<<1, 128>>>(W1, b1, W2, b2, g0, be0, m0, v0, g1, be1, m1, v1, g2, be2, m2, v2);
    prep_U<<<64, 128>>>(u, W0, b0);
    megnet_main<<<(E + 127) / 128, 256, SMEM_BYTES>>>(src, dest, edge, batch, (float*)d_out, E);
}

// round 7
// speedup vs baseline: 1.4770x; 1.0288x over previous
#include <cuda_runtime.h>
#include <cuda_fp16.h>
#include <cstdint>

// ---------------- smem layout (bytes) ----------------
#define A16_BYTES  (128 * 80)               // layer-0 fp16 A chunk, 2 buffers at 0
#define ACT_BASE   (2 * A16_BYTES)          // 20480: activations 128 x 272B (fp16)
#define ACT_STRIDE 272
#define BB_BASE    (ACT_BASE + 128 * 272)   // 55296: B fp16 chunks, 3 stages
#define BB_BYTES   (128 * 80)
#define MISC_BASE  (BB_BASE + 3 * BB_BYTES) // 86016
#define SMEM_BYTES (MISC_BASE + 2560)       // 88576

// ---------------- device scratch ----------------
__device__ __half g_W0h[128 * 384];  // [n][k] fp16 W0^T (k = 0..383)
__device__ __half g_W1h[128 * 128];  // [n][k] fp16( a0[k] * W1[k][n] )
__device__ __half g_W2h[128 * 128];  // [n][k] fp16( a1[k] * W2[k][n] )
__device__ float  g_U[64 * 128];     // U'[b][n] = b0[n] + u[b]@W0[384:,n]
__device__ float  g_b1p[128];
__device__ float  g_b2p[128];
__device__ float  g_a2v[128];
__device__ float  g_c2v[128];

// ---------------- helpers ----------------
__device__ __forceinline__ uint32_t smem_u32(const void* p) {
    uint32_t a;
    asm("{ .reg .u64 t; cvta.to.shared.u64 t, %1; cvt.u32.u64 %0, t; }" : "=r"(a) : "l"(p));
    return a;
}
__device__ __forceinline__ void cp16(void* dst, const void* src) {
    uint32_t sa = smem_u32(dst);
    asm volatile("cp.async.cg.shared.global [%0], [%1], 16;" :: "r"(sa), "l"(src) : "memory");
}
#define CPC asm volatile("cp.async.commit_group;" ::: "memory")
#define CPW(n) asm volatile("cp.async.wait_group %0;" :: "n"(n) : "memory")

__device__ __forceinline__ void ldsm4(uint32_t& r0, uint32_t& r1, uint32_t& r2, uint32_t& r3,
                                      uint32_t addr) {
    asm volatile("ldmatrix.sync.aligned.m8n8.x4.shared.b16 {%0,%1,%2,%3}, [%4];"
                 : "=r"(r0), "=r"(r1), "=r"(r2), "=r"(r3) : "r"(addr));
}
__device__ __forceinline__ void mma16816(float* c, const uint32_t* a, uint32_t b0, uint32_t b1) {
    asm volatile(
        "mma.sync.aligned.m16n8k16.row.col.f32.f16.f16.f32 "
        "{%0,%1,%2,%3}, {%4,%5,%6,%7}, {%8,%9}, {%0,%1,%2,%3};"
        : "+f"(c[0]), "+f"(c[1]), "+f"(c[2]), "+f"(c[3])
        : "r"(a[0]), "r"(a[1]), "r"(a[2]), "r"(a[3]), "r"(b0), "r"(b1));
}
__device__ __forceinline__ uint32_t h2u(__half2 h) {
    union { __half2 h; uint32_t u; } cv;
    cv.h = h;
    return cv.u;
}

// ---------------- prep kernels (parallelized) ----------------
__global__ void prep_weights(const float* __restrict__ W0, const float* __restrict__ W1,
                             const float* __restrict__ W2,
                             const float* __restrict__ g0, const float* __restrict__ v0,
                             const float* __restrict__ g1, const float* __restrict__ v1) {
    int i = blockIdx.x * 256 + threadIdx.x;
    if (i < 49152) {                         // W0h [n][k]
        int n = i / 384, k = i - n * 384;
        g_W0h[i] = __float2half(W0[k * 128 + n]);
    } else if (i < 65536) {                  // W1h [n][k] scaled by a0[k]
        int j = i - 49152;
        int n = j >> 7, k = j & 127;
        float a0 = g0[k] * rsqrtf(v0[k] + 1e-5f);
        g_W1h[j] = __float2half(a0 * W1[k * 128 + n]);
    } else if (i < 81920) {                  // W2h [n][k] scaled by a1[k]
        int j = i - 65536;
        int n = j >> 7, k = j & 127;
        float a1 = g1[k] * rsqrtf(v1[k] + 1e-5f);
        g_W2h[j] = __float2half(a1 * W2[k * 128 + n]);
    }
}

__global__ void prep_bias(const float* __restrict__ W1, const float* __restrict__ b1,
                          const float* __restrict__ W2, const float* __restrict__ b2,
                          const float* __restrict__ g0, const float* __restrict__ be0,
                          const float* __restrict__ m0, const float* __restrict__ v0,
                          const float* __restrict__ g1, const float* __restrict__ be1,
                          const float* __restrict__ m1, const float* __restrict__ v1,
                          const float* __restrict__ g2, const float* __restrict__ be2,
                          const float* __restrict__ m2, const float* __restrict__ v2) {
    __shared__ float r1[128], r2[128];
    const int n = blockIdx.x, k = threadIdx.x;
    float a0 = g0[k] * rsqrtf(v0[k] + 1e-5f);
    float c0 = be0[k] - m0[k] * a0;
    float a1 = g1[k] * rsqrtf(v1[k] + 1e-5f);
    float c1 = be1[k] - m1[k] * a1;
    r1[k] = c0 * W1[k * 128 + n];
    r2[k] = c1 * W2[k * 128 + n];
    __syncthreads();
    for (int off = 64; off; off >>= 1) {
        if (k < off) { r1[k] += r1[k + off]; r2[k] += r2[k + off]; }
        __syncthreads();
    }
    if (k == 0) {
        g_b1p[n] = b1[n] + r1[0];
        g_b2p[n] = b2[n] + r2[0];
        float a2 = g2[n] * rsqrtf(v2[n] + 1e-5f);
        g_a2v[n] = a2;
        g_c2v[n] = be2[n] - m2[n] * a2;
    }
}

__global__ void prep_U(const float* __restrict__ u, const float* __restrict__ W0,
                       const float* __restrict__ b0) {
    __shared__ float ub[128];
    int b = blockIdx.x, n = threadIdx.x;
    ub[n] = u[b * 128 + n];
    __syncthreads();
    float acc = b0[n];
    for (int k = 0; k < 128; k++) acc += ub[k] * W0[(384 + k) * 128 + n];
    g_U[b * 128 + n] = acc;
}

// ---------------- main kernel ----------------
__global__ void __launch_bounds__(256, 2)
megnet_main(const float* __restrict__ src, const float* __restrict__ dst_,
            const float* __restrict__ edg, const int* __restrict__ batch,
            float* __restrict__ out, int E) {
    extern __shared__ char sm[];
    const uint32_t sbase = smem_u32(sm);
    const int tid = threadIdx.x;
    const int w = tid >> 5, lane = tid & 31;
    const int gid = lane >> 2, tig = lane & 3;
    const int rbase = (w & 3) * 32, cbase = (w >> 2) * 64;
    const int ebase = blockIdx.x * 128;

    int* sBatch = (int*)(sm + MISC_BASE);
    float* sB1 = (float*)(sm + MISC_BASE + 512);
    float* sB2 = (float*)(sm + MISC_BASE + 1024);
    float* sA2 = (float*)(sm + MISC_BASE + 1536);
    float* sC2 = (float*)(sm + MISC_BASE + 2048);

    if (tid < 128) {
        int e = ebase + tid;
        if (e >= E) e = E - 1;
        sBatch[tid] = batch[e];
        sB1[tid] = g_b1p[tid];
        sB2[tid] = g_b2p[tid];
        sA2[tid] = g_a2v[tid];
        sC2[tid] = g_c2v[tid];
    }

    // ---- layer-0 A: direct LDG.128 (one chunk ahead) -> cvt -> STS.128 ----
    const int arow = tid >> 1, ahalf = tid & 1;
    int eA = ebase + arow;
    if (eA >= E) eA = E - 1;
    const size_t aoff = (size_t)eA * 128 + ahalf * 16;
    char* const stsp = sm + arow * 80 + ahalf * 32;   // + (cg&1)*A16_BYTES

    auto LDGA = [&](int cg, float4* f) {
        const float* T = (cg < 4) ? src : ((cg < 8) ? dst_ : edg);
        const float4* p = (const float4*)(T + aoff + (cg & 3) * 32);
        f[0] = p[0]; f[1] = p[1]; f[2] = p[2]; f[3] = p[3];
    };
    auto CVTA = [&](const float4* f, uint32_t* h) {
#pragma unroll
        for (int i = 0; i < 4; i++) {
            h[2 * i + 0] = h2u(__floats2half2_rn(f[i].x, f[i].y));
            h[2 * i + 1] = h2u(__floats2half2_rn(f[i].z, f[i].w));
        }
    };
    auto STSA = [&](int cg, const uint32_t* h) {
        char* dp = stsp + (cg & 1) * A16_BYTES;
        *(uint4*)(dp) = make_uint4(h[0], h[1], h[2], h[3]);
        *(uint4*)(dp + 16) = make_uint4(h[4], h[5], h[6], h[7]);
    };

    // ---- B prefetch: fp16 weight chunk [128n x 32k], 3-stage ring ----
    auto PFB = [&](int cg) {
        const __half* Wh; int kb, ldk;
        if (cg < 12)      { Wh = g_W0h; kb = cg * 32;        ldk = 384; }
        else if (cg < 16) { Wh = g_W1h; kb = (cg - 12) * 32; ldk = 128; }
        else              { Wh = g_W2h; kb = (cg - 16) * 32; ldk = 128; }
        char* base = sm + BB_BASE + (cg % 3) * BB_BYTES;
#pragma unroll
        for (int i = 0; i < 2; i++) {
            int f = tid + i * 256;           // 512 16B-units
            int n = f >> 2, kh = f & 3;
            cp16(base + n * 80 + kh * 16,
                 (const char*)(Wh + (size_t)n * ldk + kb) + kh * 16);
        }
        CPC;
    };

    float acc[2][8][4];
#pragma unroll
    for (int mt = 0; mt < 2; mt++)
#pragma unroll
        for (int nt = 0; nt < 8; nt++)
#pragma unroll
            for (int i = 0; i < 4; i++) acc[mt][nt][i] = 0.f;

    // ---- epilogue: acc -> (+U' or +b1'), relu, fp16 -> activation smem ----
    auto EPI = [&](bool first) {
        __syncthreads();                      // all warps done with previous MMA reads
#pragma unroll
        for (int mt = 0; mt < 2; mt++) {
#pragma unroll
            for (int nt = 0; nt < 8; nt++) {
                const int col = cbase + nt * 8 + 2 * tig;
#pragma unroll
                for (int rh = 0; rh < 2; rh++) {
                    const int row = rbase + mt * 16 + gid + rh * 8;
                    float ax, ay;
                    if (first) {
                        const float2 uv = *(const float2*)&g_U[(size_t)sBatch[row] * 128 + col];
                        ax = uv.x; ay = uv.y;
                    } else {
                        ax = sB1[col]; ay = sB1[col + 1];
                    }
                    float* c4 = acc[mt][nt];
                    float x = fmaxf(c4[rh * 2 + 0] + ax, 0.f);
                    float y = fmaxf(c4[rh * 2 + 1] + ay, 0.f);
                    *(__half2*)(sm + ACT_BASE + row * ACT_STRIDE + ((col >> 3) << 4) +
                                (col & 7) * 2) = __floats2half2_rn(x, y);
                    c4[rh * 2 + 0] = 0.f;
                    c4[rh * 2 + 1] = 0.f;
                }
            }
        }
    };

    // ---------------- pipeline: 20 chunks (12 + 4 + 4) ----------------
    PFB(0); PFB(1);
    float4 fA[4];
    uint32_t hA[8];
    LDGA(0, fA);
    CVTA(fA, hA);

#pragma unroll 1
    for (int cg = 0; cg < 20; cg++) {
        if (cg == 12) EPI(true);
        else if (cg == 16) EPI(false);

        if (cg < 19) { CPW(1); } else { CPW(0); }
        if (cg < 12) STSA(cg, hA);
        __syncthreads();          // publish A(cg) STS + B(cg) cp.async to all threads

        if (cg + 2 < 20) PFB(cg + 2);
        if (cg + 1 < 12) LDGA(cg + 1, fA);   // overlap global latency with MMA below

        // ---- MMA for chunk cg: warp tile 32m x 64n, K=32 (2 k-steps of 16) ----
        uint32_t aB; int aS;
        if (cg < 12) { aB = sbase + (cg & 1) * A16_BYTES; aS = 80; }
        else {
            aB = sbase + ACT_BASE + ((cg < 16) ? (cg - 12) : (cg - 16)) * 64;
            aS = ACT_STRIDE;
        }
        const uint32_t bB = sbase + BB_BASE + (cg % 3) * BB_BYTES;

#pragma unroll
        for (int ks = 0; ks < 2; ks++) {
            uint32_t a[2][4];
#pragma unroll
            for (int mt = 0; mt < 2; mt++) {
                uint32_t ad = aB + (uint32_t)(rbase + mt * 16 + (lane & 15)) * aS +
                              ks * 32 + (lane >> 4) * 16;
                ldsm4(a[mt][0], a[mt][1], a[mt][2], a[mt][3], ad);
            }
            uint32_t b[4][4];
#pragma unroll
            for (int nt2 = 0; nt2 < 4; nt2++) {
                uint32_t bd = bB + (uint32_t)(cbase + nt2 * 16 + (lane & 7) +
                                              ((lane >> 4) & 1) * 8) * 80 +
                              ks * 32 + ((lane >> 3) & 1) * 16;
                ldsm4(b[nt2][0], b[nt2][1], b[nt2][2], b[nt2][3], bd);
            }
#pragma unroll
            for (int mt = 0; mt < 2; mt++)
#pragma unroll
                for (int nt2 = 0; nt2 < 4; nt2++) {
                    mma16816(acc[mt][nt2 * 2 + 0], a[mt], b[nt2][0], b[nt2][1]);
                    mma16816(acc[mt][nt2 * 2 + 1], a[mt], b[nt2][2], b[nt2][3]);
                }
        }

        if (cg + 1 < 12) CVTA(fA, hA);       // after MMA: loads have landed
    }

    // ---------------- final epilogue: + b2', relu, BN2 affine, store ----------------
    const int Ev = E - ebase;
#pragma unroll
    for (int mt = 0; mt < 2; mt++) {
#pragma unroll
        for (int nt = 0; nt < 8; nt++) {
            const int col = cbase + nt * 8 + 2 * tig;
            const float bx = sB2[col], by = sB2[col + 1];
            const float axm = sA2[col], aym = sA2[col + 1];
            const float cxm = sC2[col], cym = sC2[col + 1];
#pragma unroll
            for (int rh = 0; rh < 2; rh++) {
                const int row = rbase + mt * 16 + gid + rh * 8;
                if (row < Ev) {
                    float* c4 = acc[mt][nt];
                    float2 v;
                    v.x = fmaxf(c4[rh * 2 + 0] + bx, 0.f) * axm + cxm;
                    v.y = fmaxf(c4[rh * 2 + 1] + by, 0.f) * aym + cym;
                    *(float2*)&out[(size_t)(ebase + row) * 128 + col] = v;
                }
            }
        }
    }
}

// ---------------- launch ----------------
extern "C" void kernel_launch(void* const* d_in, const int* in_sizes, int n_in,
                              void* d_out, int out_size) {
    const float* src  = (const float*)d_in[0];
    const float* dest = (const float*)d_in[1];
    const float* edge = (const float*)d_in[2];
    const float* u    = (const float*)d_in[3];
    const int*   batch = (const int*)d_in[4];
    const float* W0 = (const float*)d_in[5];
    const float* b0 = (const float*)d_in[6];
    const float* W1 = (const float*)d_in[7];
    const float* b1 = (const float*)d_in[8];
    const float* W2 = (const float*)d_in[9];
    const float* b2 = (const float*)d_in[10];
    const float* g0 = (const float*)d_in[11];
    const float* be0 = (const float*)d_in[12];
    const float* m0 = (const float*)d_in[13];
    const float* v0 = (const float*)d_in[14];
    const float* g1 = (const float*)d_in[15];
    const float* be1 = (const float*)d_in[16];
    const float* m1 = (const float*)d_in[17];
    const float* v1 = (const float*)d_in[18];
    const float* g2 = (const float*)d_in[19];
    const float* be2 = (const float*)d_in[20];
    const float* m2 = (const float*)d_in[21];
    const float* v2 = (const float*)d_in[22];

    int E = in_sizes[0] / 128;

    cudaFuncSetAttribute(megnet_main, cudaFuncAttributeMaxDynamicSharedMemorySize, SMEM_BYTES);

    prep_weights<<<320, 256>>>(W0, W1, W2, g0, v0, g1, v1);
    prep_bias<<<128, 128>>>(W1, b1, W2, b2, g0, be0, m0, v0, g1, be1, m1, v1,
                            g2, be2, m2, v2);
    prep_U<<<64, 128>>>(u, W0, b0);
    megnet_main<<<(E + 127) / 128, 256, SMEM_BYTES>>>(src, dest, edge, batch, (float*)d_out, E);
}

// round 8
// speedup vs baseline: 1.5720x; 1.0643x over previous
#include <cuda_runtime.h>
#include <cuda_fp16.h>
#include <cstdint>

// ---------------- smem layout (bytes) ----------------
#define STG_STRIDE 144                  // fp32 staging row: 128B data + 16B pad
#define STG_BYTES  (128 * 144)          // 18432 per buffer, 2 buffers at 0
#define ACT_BASE   (2 * STG_BYTES)      // 36864: activations 128 x 272B (fp16, padded)
#define ACT_STRIDE 272
#define A16_BYTES  (128 * 80)           // 10240: layer-0 fp16 A chunk (2 bufs alias ACT region)
#define BB_BASE    (ACT_BASE + 128 * 272)   // 71680: B fp16 chunks, 3 stages x 10240
#define BB_BYTES   (128 * 80)
#define MISC_BASE  (BB_BASE + 3 * BB_BYTES) // 102400
#define SMEM_BYTES (MISC_BASE + 2560)       // 104960

// ---------------- device scratch ----------------
__device__ __half g_W0h[128 * 384];  // [n][k] fp16 W0^T (k = 0..383)
__device__ __half g_W1h[128 * 128];  // [n][k] fp16( a0[k] * W1[k][n] )
__device__ __half g_W2h[128 * 128];  // [n][k] fp16( a1[k] * W2[k][n] )
__device__ float  g_U[64 * 128];     // U'[b][n] = b0[n] + u[b]@W0[384:,n]
__device__ float  g_b1p[128];
__device__ float  g_b2p[128];
__device__ float  g_a2v[128];
__device__ float  g_c2v[128];

// ---------------- helpers ----------------
__device__ __forceinline__ uint32_t smem_u32(const void* p) {
    uint32_t a;
    asm("{ .reg .u64 t; cvta.to.shared.u64 t, %1; cvt.u32.u64 %0, t; }" : "=r"(a) : "l"(p));
    return a;
}
__device__ __forceinline__ void cp16(void* dst, const void* src) {
    uint32_t sa = smem_u32(dst);
    asm volatile("cp.async.cg.shared.global [%0], [%1], 16;" :: "r"(sa), "l"(src) : "memory");
}
#define CPC asm volatile("cp.async.commit_group;" ::: "memory")
#define CPW(n) asm volatile("cp.async.wait_group %0;" :: "n"(n) : "memory")

__device__ __forceinline__ void ldsm4(uint32_t& r0, uint32_t& r1, uint32_t& r2, uint32_t& r3,
                                      uint32_t addr) {
    asm volatile("ldmatrix.sync.aligned.m8n8.x4.shared.b16 {%0,%1,%2,%3}, [%4];"
                 : "=r"(r0), "=r"(r1), "=r"(r2), "=r"(r3) : "r"(addr));
}
__device__ __forceinline__ void mma16816(float* c, const uint32_t* a, uint32_t b0, uint32_t b1) {
    asm volatile(
        "mma.sync.aligned.m16n8k16.row.col.f32.f16.f16.f32 "
        "{%0,%1,%2,%3}, {%4,%5,%6,%7}, {%8,%9}, {%0,%1,%2,%3};"
        : "+f"(c[0]), "+f"(c[1]), "+f"(c[2]), "+f"(c[3])
        : "r"(a[0]), "r"(a[1]), "r"(a[2]), "r"(a[3]), "r"(b0), "r"(b1));
}
__device__ __forceinline__ uint32_t h2u(__half2 h) {
    union { __half2 h; uint32_t u; } cv;
    cv.h = h;
    return cv.u;
}

// ---------------- prep kernels (parallelized) ----------------
__global__ void prep_weights(const float* __restrict__ W0, const float* __restrict__ W1,
                             const float* __restrict__ W2,
                             const float* __restrict__ g0, const float* __restrict__ v0,
                             const float* __restrict__ g1, const float* __restrict__ v1) {
    int i = blockIdx.x * 256 + threadIdx.x;
    if (i < 49152) {                         // W0h [n][k]
        int n = i / 384, k = i - n * 384;
        g_W0h[i] = __float2half(W0[k * 128 + n]);
    } else if (i < 65536) {                  // W1h [n][k] scaled by a0[k]
        int j = i - 49152;
        int n = j >> 7, k = j & 127;
        float a0 = g0[k] * rsqrtf(v0[k] + 1e-5f);
        g_W1h[j] = __float2half(a0 * W1[k * 128 + n]);
    } else if (i < 81920) {                  // W2h [n][k] scaled by a1[k]
        int j = i - 65536;
        int n = j >> 7, k = j & 127;
        float a1 = g1[k] * rsqrtf(v1[k] + 1e-5f);
        g_W2h[j] = __float2half(a1 * W2[k * 128 + n]);
    }
}

__global__ void prep_bias(const float* __restrict__ W1, const float* __restrict__ b1,
                          const float* __restrict__ W2, const float* __restrict__ b2,
                          const float* __restrict__ g0, const float* __restrict__ be0,
                          const float* __restrict__ m0, const float* __restrict__ v0,
                          const float* __restrict__ g1, const float* __restrict__ be1,
                          const float* __restrict__ m1, const float* __restrict__ v1,
                          const float* __restrict__ g2, const float* __restrict__ be2,
                          const float* __restrict__ m2, const float* __restrict__ v2) {
    __shared__ float r1[128], r2[128];
    const int n = blockIdx.x, k = threadIdx.x;
    float a0 = g0[k] * rsqrtf(v0[k] + 1e-5f);
    float c0 = be0[k] - m0[k] * a0;
    float a1 = g1[k] * rsqrtf(v1[k] + 1e-5f);
    float c1 = be1[k] - m1[k] * a1;
    r1[k] = c0 * W1[k * 128 + n];
    r2[k] = c1 * W2[k * 128 + n];
    __syncthreads();
    for (int off = 64; off; off >>= 1) {
        if (k < off) { r1[k] += r1[k + off]; r2[k] += r2[k + off]; }
        __syncthreads();
    }
    if (k == 0) {
        g_b1p[n] = b1[n] + r1[0];
        g_b2p[n] = b2[n] + r2[0];
        float a2 = g2[n] * rsqrtf(v2[n] + 1e-5f);
        g_a2v[n] = a2;
        g_c2v[n] = be2[n] - m2[n] * a2;
    }
}

__global__ void prep_U(const float* __restrict__ u, const float* __restrict__ W0,
                       const float* __restrict__ b0) {
    __shared__ float ub[128];
    int b = blockIdx.x, n = threadIdx.x;
    ub[n] = u[b * 128 + n];
    __syncthreads();
    float acc = b0[n];
    for (int k = 0; k < 128; k++) acc += ub[k] * W0[(384 + k) * 128 + n];
    g_U[b * 128 + n] = acc;
}

// ---------------- main kernel ----------------
__global__ void __launch_bounds__(256, 2)
megnet_main(const float* __restrict__ src, const float* __restrict__ dst_,
            const float* __restrict__ edg, const int* __restrict__ batch,
            float* __restrict__ out, int E) {
    extern __shared__ char sm[];
    const uint32_t sbase = smem_u32(sm);
    const int tid = threadIdx.x;
    const int w = tid >> 5, lane = tid & 31;
    const int gid = lane >> 2, tig = lane & 3;
    const int rbase = (w & 3) * 32, cbase = (w >> 2) * 64;
    const int ebase = blockIdx.x * 128;

    int* sBatch = (int*)(sm + MISC_BASE);
    float* sB1 = (float*)(sm + MISC_BASE + 512);
    float* sB2 = (float*)(sm + MISC_BASE + 1024);
    float* sA2 = (float*)(sm + MISC_BASE + 1536);
    float* sC2 = (float*)(sm + MISC_BASE + 2048);

    if (tid < 128) {
        int e = ebase + tid;
        if (e >= E) e = E - 1;
        sBatch[tid] = batch[e];
        sB1[tid] = g_b1p[tid];
        sB2[tid] = g_b2p[tid];
        sA2[tid] = g_a2v[tid];
        sC2[tid] = g_c2v[tid];
    }

    // ---- PFA: stage layer-0 fp32 chunk cg into staging[cg&1] (own cp.async group) ----
    auto PFA = [&](int cg) {
        if (cg < 12) {
            const float* T = (cg < 4) ? src : ((cg < 8) ? dst_ : edg);
            const int coff = (cg & 3) * 32;
            char* base = sm + (cg & 1) * STG_BYTES;
#pragma unroll
            for (int i = 0; i < 4; i++) {
                int f = tid + i * 256;           // 1024 16B-units
                int row = f >> 3, u = f & 7;
                int e = ebase + row;
                if (e >= E) e = E - 1;
                cp16(base + row * STG_STRIDE + u * 16,
                     (const char*)(T + (size_t)e * 128 + coff) + u * 16);
            }
        }
        CPC;                                      // empty group when cg >= 12
    };
    // ---- PFB: fp16 weight chunk [128n x 32k] into BB[cg%3] (own group) ----
    auto PFB = [&](int cg) {
        if (cg < 20) {
            const __half* Wh; int kb, ldk;
            if (cg < 12)      { Wh = g_W0h; kb = cg * 32;        ldk = 384; }
            else if (cg < 16) { Wh = g_W1h; kb = (cg - 12) * 32; ldk = 128; }
            else              { Wh = g_W2h; kb = (cg - 16) * 32; ldk = 128; }
            char* base = sm + BB_BASE + (cg % 3) * BB_BYTES;
#pragma unroll
            for (int i = 0; i < 2; i++) {
                int f = tid + i * 256;           // 512 16B-units
                int n = f >> 2, kh = f & 3;
                cp16(base + n * 80 + kh * 16,
                     (const char*)(Wh + (size_t)n * ldk + kb) + kh * 16);
            }
        }
        CPC;                                      // empty group when cg >= 20
    };
    // ---- CONV: staged fp32 chunk cg -> fp16 A16[cg&1] (stride 80) ----
    auto CONV = [&](int cg) {
        const int buf = cg & 1;
        const int r = tid & 127, h = tid >> 7;
        const char* sp = sm + buf * STG_BYTES + r * STG_STRIDE + h * 64;
        float4 f0 = *(const float4*)(sp);
        float4 f1 = *(const float4*)(sp + 16);
        float4 f2 = *(const float4*)(sp + 32);
        float4 f3 = *(const float4*)(sp + 48);
        uint4 o0, o1;
        o0.x = h2u(__floats2half2_rn(f0.x, f0.y));
        o0.y = h2u(__floats2half2_rn(f0.z, f0.w));
        o0.z = h2u(__floats2half2_rn(f1.x, f1.y));
        o0.w = h2u(__floats2half2_rn(f1.z, f1.w));
        o1.x = h2u(__floats2half2_rn(f2.x, f2.y));
        o1.y = h2u(__floats2half2_rn(f2.z, f2.w));
        o1.z = h2u(__floats2half2_rn(f3.x, f3.y));
        o1.w = h2u(__floats2half2_rn(f3.z, f3.w));
        char* dp = sm + ACT_BASE + buf * A16_BYTES + r * 80 + h * 32;
        *(uint4*)(dp) = o0;
        *(uint4*)(dp + 16) = o1;
    };

    float acc[2][8][4];
#pragma unroll
    for (int mt = 0; mt < 2; mt++)
#pragma unroll
        for (int nt = 0; nt < 8; nt++)
#pragma unroll
            for (int i = 0; i < 4; i++) acc[mt][nt][i] = 0.f;

    // ---- epilogue: acc -> (+U' or +b1'), relu, fp16 -> activation smem ----
    auto EPI = [&](bool first) {
        __syncthreads();                      // all warps done with previous MMA reads
#pragma unroll
        for (int mt = 0; mt < 2; mt++) {
#pragma unroll
            for (int nt = 0; nt < 8; nt++) {
                const int col = cbase + nt * 8 + 2 * tig;
#pragma unroll
                for (int rh = 0; rh < 2; rh++) {
                    const int row = rbase + mt * 16 + gid + rh * 8;
                    float ax, ay;
                    if (first) {
                        const float2 uv = *(const float2*)&g_U[(size_t)sBatch[row] * 128 + col];
                        ax = uv.x; ay = uv.y;
                    } else {
                        ax = sB1[col]; ay = sB1[col + 1];
                    }
                    float* c4 = acc[mt][nt];
                    float x = fmaxf(c4[rh * 2 + 0] + ax, 0.f);
                    float y = fmaxf(c4[rh * 2 + 1] + ay, 0.f);
                    *(__half2*)(sm + ACT_BASE + row * ACT_STRIDE + ((col >> 3) << 4) +
                                (col & 7) * 2) = __floats2half2_rn(x, y);
                    c4[rh * 2 + 0] = 0.f;
                    c4[rh * 2 + 1] = 0.f;
                }
            }
        }
    };

    // ---------------- pipeline: 20 chunks (12 + 4 + 4), 1 barrier/chunk ----------------
    __syncthreads();     // sBatch/bias tables visible
    PFA(0); PFB(0);      // groups 0,1
    PFA(1); PFB(1);      // groups 2,3
    CPW(2);              // A(0), B(0) complete
    __syncthreads();     // publish staged A(0)/B(0)
    CONV(0);             // A16[0] ready (published by bar in iter 0)

#pragma unroll 1
    for (int cg = 0; cg < 20; cg++) {
        if (cg == 12) EPI(true);
        else if (cg == 16) EPI(false);

        // After iter cg-1, newest groups are A(cg+1), B(cg+1).
        // CPW(1): everything except B(cg+1) complete -> A(cg+1) (for CONV) and B(cg) ready.
        CPW(1);
        __syncthreads();          // publish cp.async data + last iter's CONV to all threads

        if (cg + 1 < 12) CONV(cg + 1);   // convert NEXT chunk; consumed after bar(cg+1)
        PFA(cg + 2);                      // (empty group when cg+2 >= 12)
        PFB(cg + 2);                      // (empty group when cg+2 >= 20)

        // ---- MMA for chunk cg: warp tile 32m x 64n, K=32 (2 k-steps of 16) ----
        uint32_t aB; int aS;
        if (cg < 12) { aB = sbase + ACT_BASE + (cg & 1) * A16_BYTES; aS = 80; }
        else {
            aB = sbase + ACT_BASE + ((cg < 16) ? (cg - 12) : (cg - 16)) * 64;
            aS = ACT_STRIDE;
        }
        const uint32_t bB = sbase + BB_BASE + (cg % 3) * BB_BYTES;

#pragma unroll
        for (int ks = 0; ks < 2; ks++) {
            uint32_t a[2][4];
#pragma unroll
            for (int mt = 0; mt < 2; mt++) {
                uint32_t ad = aB + (uint32_t)(rbase + mt * 16 + (lane & 15)) * aS +
                              ks * 32 + (lane >> 4) * 16;
                ldsm4(a[mt][0], a[mt][1], a[mt][2], a[mt][3], ad);
            }
            uint32_t b[4][4];
#pragma unroll
            for (int nt2 = 0; nt2 < 4; nt2++) {
                uint32_t bd = bB + (uint32_t)(cbase + nt2 * 16 + (lane & 7) +
                                              ((lane >> 4) & 1) * 8) * 80 +
                              ks * 32 + ((lane >> 3) & 1) * 16;
                ldsm4(b[nt2][0], b[nt2][1], b[nt2][2], b[nt2][3], bd);
            }
#pragma unroll
            for (int mt = 0; mt < 2; mt++)
#pragma unroll
                for (int nt2 = 0; nt2 < 4; nt2++) {
                    mma16816(acc[mt][nt2 * 2 + 0], a[mt], b[nt2][0], b[nt2][1]);
                    mma16816(acc[mt][nt2 * 2 + 1], a[mt], b[nt2][2], b[nt2][3]);
                }
        }
    }

    // ---------------- final epilogue: + b2', relu, BN2 affine, store ----------------
    const int Ev = E - ebase;
#pragma unroll
    for (int mt = 0; mt < 2; mt++) {
#pragma unroll
        for (int nt = 0; nt < 8; nt++) {
            const int col = cbase + nt * 8 + 2 * tig;
            const float bx = sB2[col], by = sB2[col + 1];
            const float axm = sA2[col], aym = sA2[col + 1];
            const float cxm = sC2[col], cym = sC2[col + 1];
#pragma unroll
            for (int rh = 0; rh < 2; rh++) {
                const int row = rbase + mt * 16 + gid + rh * 8;
                if (row < Ev) {
                    float* c4 = acc[mt][nt];
                    float2 v;
                    v.x = fmaxf(c4[rh * 2 + 0] + bx, 0.f) * axm + cxm;
                    v.y = fmaxf(c4[rh * 2 + 1] + by, 0.f) * aym + cym;
                    *(float2*)&out[(size_t)(ebase + row) * 128 + col] = v;
                }
            }
        }
    }
}

// ---------------- launch ----------------
extern "C" void kernel_launch(void* const* d_in, const int* in_sizes, int n_in,
                              void* d_out, int out_size) {
    const float* src  = (const float*)d_in[0];
    const float* dest = (const float*)d_in[1];
    const float* edge = (const float*)d_in[2];
    const float* u    = (const float*)d_in[3];
    const int*   batch = (const int*)d_in[4];
    const float* W0 = (const float*)d_in[5];
    const float* b0 = (const float*)d_in[6];
    const float* W1 = (const float*)d_in[7];
    const float* b1 = (const float*)d_in[8];
    const float* W2 = (const float*)d_in[9];
    const float* b2 = (const float*)d_in[10];
    const float* g0 = (const float*)d_in[11];
    const float* be0 = (const float*)d_in[12];
    const float* m0 = (const float*)d_in[13];
    const float* v0 = (const float*)d_in[14];
    const float* g1 = (const float*)d_in[15];
    const float* be1 = (const float*)d_in[16];
    const float* m1 = (const float*)d_in[17];
    const float* v1 = (const float*)d_in[18];
    const float* g2 = (const float*)d_in[19];
    const float* be2 = (const float*)d_in[20];
    const float* m2 = (const float*)d_in[21];
    const float* v2 = (const float*)d_in[22];

    int E = in_sizes[0] / 128;

    cudaFuncSetAttribute(megnet_main, cudaFuncAttributeMaxDynamicSharedMemorySize, SMEM_BYTES);

    prep_weights<<<320, 256>>>(W0, W1, W2, g0, v0, g1, v1);
    prep_bias<<<128, 128>>>(W1, b1, W2, b2, g0, be0, m0, v0, g1, be1, m1, v1,
                            g2, be2, m2, v2);
    prep_U<<<64, 128>>>(u, W0, b0);
    megnet_main<<<(E + 127) / 128, 256, SMEM_BYTES>>>(src, dest, edge, batch, (float*)d_out, E);
}